// round 11
// baseline (speedup 1.0000x reference)
#include <cuda_runtime.h>
#include <math.h>
#include <stdint.h>

#define BATCH 4
#define CIN 64
#define COUT 64
#define HH 192
#define WW 192
#define HW (HH*WW)          // 36864
#define CHW (CIN*HW)
#define PIX (BATCH*HW)      // 147456
#define KROWS 576
#define NTILE2 (PIX/256)    // 576 tiles of 256 pixels
#define BPITCH 580          // B row pitch in u32 (576 + 4 pad)
#define SMEM_A  (256*32*4)               // 32 KB per A stage
#define SMEM_B2 (64*BPITCH*4)            // 148480
#define SMEM_B1 (32*BPITCH*4)            // 74240
#define SMEM_K2 (SMEM_B2 + 2*SMEM_A)     // 214016
#define SMEM_K1 (SMEM_B1 + 2*SMEM_A)     // 139776

__device__ __forceinline__ uint32_t smem_u32(const void* p) {
    uint32_t a;
    asm("{ .reg .u64 t; cvta.to.shared.u64 t, %1; cvt.u32.u64 %0, t; }" : "=r"(a) : "l"(p));
    return a;
}
__device__ __forceinline__ uint32_t tf32cvt(float f) {
    uint32_t u; asm("cvt.rna.tf32.f32 %0, %1;" : "=r"(u) : "f"(f)); return u;
}
__device__ __forceinline__ void mma_tf32(float* d, uint32_t a0, uint32_t a1,
                                         uint32_t a2, uint32_t a3,
                                         uint32_t b0, uint32_t b1) {
    asm volatile(
        "mma.sync.aligned.m16n8k8.row.col.f32.tf32.tf32.f32 "
        "{%0,%1,%2,%3}, {%4,%5,%6,%7}, {%8,%9}, {%0,%1,%2,%3};"
        : "+f"(d[0]), "+f"(d[1]), "+f"(d[2]), "+f"(d[3])
        : "r"(a0), "r"(a1), "r"(a2), "r"(a3), "r"(b0), "r"(b1));
}
__device__ __forceinline__ uint32_t swz(uint32_t byte) {
    return byte ^ ((byte >> 3) & 0x70u);
}

// ---- scratch (device globals) ----
__device__ uint32_t g_wB1[32*BPITCH];
__device__ uint32_t g_wB2[64*BPITCH];
__device__ float    g_off[BATCH*27*HW];
__device__ float    g_mid[BATCH*COUT*HW];
__device__ float    g_part[NTILE2*128];    // per-tile [64ch][sum,sq]
__device__ float    g_scale[COUT];
__device__ float    g_shift[COUT];

// ---------------------------------------------------------------------------
// K0: pack tf32 weight matrices
// ---------------------------------------------------------------------------
__global__ void k0_prep(const float* __restrict__ wp, const float* __restrict__ wm,
                        const float* __restrict__ wc) {
    int i = blockIdx.x * 256 + threadIdx.x;
    if (i < 32*BPITCH) {
        int n = i / BPITCH, u = i - n*BPITCH;
        uint32_t val = 0;
        if (u < 576 && n < 27) {
            int tap = u >> 6, c = u & 63;
            float w = (n < 18) ? wp[n*KROWS + c*9 + tap] : wm[(n-18)*KROWS + c*9 + tap];
            val = tf32cvt(w);
        }
        g_wB1[i] = val;
    }
    if (i < 64*BPITCH) {
        int n = i / BPITCH, u = i - n*BPITCH;
        uint32_t val = 0;
        if (u < 576) {
            int tap = u >> 6, c = u & 63;
            val = tf32cvt(wc[n*KROWS + c*9 + tap]);
        }
        g_wB2[i] = val;
    }
}

// ---------------------------------------------------------------------------
// K1: offset/mask conv as tf32 HMMA GEMM, prefetch-interleaved.
// ---------------------------------------------------------------------------
__global__ void __launch_bounds__(512, 1) k1_mma(const float* __restrict__ x,
                                                 const float* __restrict__ bp,
                                                 const float* __restrict__ bm) {
    extern __shared__ __align__(1024) char smraw[];
    uint32_t* B1s = (uint32_t*)smraw;
    const uint32_t AbaseS = smem_u32(smraw) + SMEM_B1;

    int tid = threadIdx.x;
    {
        const uint4* src = (const uint4*)g_wB1;
        uint4* dst = (uint4*)B1s;
        for (int i = tid; i < (32*BPITCH)/4; i += 512) dst[i] = src[i];
    }
    __syncthreads();

    int tile = blockIdx.x;
    int lp   = tid & 255;
    int uh   = tid >> 8;
    int b    = tile / 144;
    int rembase = (tile - b*144) * 256;
    int rem  = rembase + lp;
    int y    = rem / WW, xx = rem - y*WW;
    const float* xb = x + (size_t)b*CHW;

    int lane = tid & 31, w = tid >> 5;
    int r = lane >> 2, t = lane & 3;

    float d[16];
#pragma unroll
    for (int i = 0; i < 16; i++) d[i] = 0.f;

#define PREF1(gr, qq) do { \
    int cb = chalf + uh*16 + (qq)*4; \
    _Pragma("unroll") for (int ci = 0; ci < 4; ci++) \
        gr[ci] = valid ? __ldg(xs + (size_t)(cb + ci)*HW) : 0.f; \
} while(0)

#define COMB1(gr, qq) do { \
    uint32_t v[4]; \
    _Pragma("unroll") for (int ci = 0; ci < 4; ci++) v[ci] = tf32cvt(gr[ci]); \
    uint32_t byte = swz((uint32_t)lp*128u + (uint32_t)(uh*16 + (qq)*4)*4u); \
    asm volatile("st.shared.v4.b32 [%0], {%1,%2,%3,%4};" \
        :: "r"(Abuf_w + byte), "r"(v[0]), "r"(v[1]), "r"(v[2]), "r"(v[3]) : "memory"); \
} while(0)

#define MMACH1(kc) do { \
    uint32_t brow = (uint32_t)(w*16 + r)*128u; \
    uint32_t bcol = (uint32_t)((kc)*8 + t)*4u; \
    uint32_t a0, a1, a2, a3; \
    asm volatile("ld.shared.b32 %0, [%1];" : "=r"(a0) : "r"(Abuf_r + swz(brow + bcol))); \
    asm volatile("ld.shared.b32 %0, [%1];" : "=r"(a1) : "r"(Abuf_r + swz(brow + 1024u + bcol))); \
    asm volatile("ld.shared.b32 %0, [%1];" : "=r"(a2) : "r"(Abuf_r + swz(brow + bcol + 16u))); \
    asm volatile("ld.shared.b32 %0, [%1];" : "=r"(a3) : "r"(Abuf_r + swz(brow + 1024u + bcol + 16u))); \
    int ub = s*32 + (kc)*8 + t; \
    _Pragma("unroll") for (int nt = 0; nt < 4; nt++) { \
        int nrow = nt*8 + r; \
        uint32_t b0 = B1s[nrow*BPITCH + ub]; \
        uint32_t b1 = B1s[nrow*BPITCH + ub + 4]; \
        mma_tf32(d + nt*4, a0, a1, a2, a3, b0, b1); \
    } \
} while(0)

    float gA[4], gB[4];
#pragma unroll 1
    for (int s = -1; s < 18; s++) {
        int sp = s + 1;
        bool prod = (sp < 18);
        int n  = sp >> 1;
        int ty = n / 3, tx = n - 3*ty;
        int iy = y + ty - 1, ix = xx + tx - 1;
        bool valid = prod && (iy >= 0) && (iy < HH) && (ix >= 0) && (ix < WW);
        int chalf = (sp & 1) * 32;
        const float* xs = xb + iy*WW + ix;
        uint32_t Abuf_w = AbaseS + (uint32_t)((sp & 1) * SMEM_A);
        uint32_t Abuf_r = AbaseS + (uint32_t)((s & 1) * SMEM_A);

        if (prod) PREF1(gA, 0);
        if (s >= 0) MMACH1(0);
        if (prod) { PREF1(gB, 1); COMB1(gA, 0); }
        if (s >= 0) MMACH1(1);
        if (prod) { PREF1(gA, 2); COMB1(gB, 1); }
        if (s >= 0) MMACH1(2);
        if (prod) { PREF1(gB, 3); COMB1(gA, 2); }
        if (s >= 0) MMACH1(3);
        if (prod) COMB1(gB, 3);
        __syncthreads();
    }

    float* op = g_off + (size_t)b*27*HW + (rembase + w*16);
#pragma unroll
    for (int nt = 0; nt < 4; nt++) {
#pragma unroll
        for (int e = 0; e < 2; e++) {
            int o = nt*8 + 2*t + e;
            if (o >= 27) continue;
            float add = (o < 18) ? __ldg(bp + o) : __ldg(bm + o - 18);
            float v0 = d[nt*4 + e]     + add;
            float v1 = d[nt*4 + 2 + e] + add;
            if (o >= 18) {
                v0 = 1.f / (1.f + expf(-v0));
                v1 = 1.f / (1.f + expf(-v1));
            }
            op[(size_t)o*HW + r]     = v0;
            op[(size_t)o*HW + r + 8] = v1;
        }
    }
}

// ---------------------------------------------------------------------------
// K2: deformable sampling + main conv, prefetch-interleaved HMMA,
//     fused per-tile BN partial statistics.
// ---------------------------------------------------------------------------
__global__ void __launch_bounds__(512, 1) k2_mma(const float* __restrict__ x) {
    extern __shared__ __align__(1024) char smraw[];
    uint32_t* B2s = (uint32_t*)smraw;
    const uint32_t AbaseS = smem_u32(smraw) + SMEM_B2;

    int tid = threadIdx.x;
    {
        const uint4* src = (const uint4*)g_wB2;
        uint4* dst = (uint4*)B2s;
        for (int i = tid; i < (64*BPITCH)/4; i += 512) dst[i] = src[i];
    }
    __syncthreads();

    int tile = blockIdx.x;
    int lp   = tid & 255;
    int uh   = tid >> 8;
    int b    = tile / 144;
    int rembase = (tile - b*144) * 256;
    int rem  = rembase + lp;
    int y    = rem / WW, xx = rem - y*WW;
    const float* xb   = x + (size_t)b*CHW;
    const float* offp = g_off + (size_t)b*27*HW + rem;

    int lane = tid & 31, w = tid >> 5;
    int r = lane >> 2, t = lane & 3;

    float d[32];
#pragma unroll
    for (int i = 0; i < 32; i++) d[i] = 0.f;

    float cw0=0, cw1=0, cw2=0, cw3=0;
    const float *p0 = xb, *p1 = xb, *p2 = xb, *p3 = xb;

#define PREF2(gr, qq) do { \
    int cb = chalf + uh*16 + (qq)*4; \
    _Pragma("unroll") for (int ci = 0; ci < 4; ci++) { \
        size_t off = (size_t)(cb + ci)*HW; \
        gr[ci*4+0] = __ldg(p0 + off); gr[ci*4+1] = __ldg(p1 + off); \
        gr[ci*4+2] = __ldg(p2 + off); gr[ci*4+3] = __ldg(p3 + off); \
    } \
} while(0)

#define COMB2(gr, qq) do { \
    uint32_t v[4]; \
    _Pragma("unroll") for (int ci = 0; ci < 4; ci++) { \
        float sv = cw0*gr[ci*4+0] + cw1*gr[ci*4+1] + cw2*gr[ci*4+2] + cw3*gr[ci*4+3]; \
        v[ci] = tf32cvt(sv); \
    } \
    uint32_t byte = swz((uint32_t)lp*128u + (uint32_t)(uh*16 + (qq)*4)*4u); \
    asm volatile("st.shared.v4.b32 [%0], {%1,%2,%3,%4};" \
        :: "r"(Abuf_w + byte), "r"(v[0]), "r"(v[1]), "r"(v[2]), "r"(v[3]) : "memory"); \
} while(0)

#define MMACH2(kc) do { \
    uint32_t brow = (uint32_t)(w*16 + r)*128u; \
    uint32_t bcol = (uint32_t)((kc)*8 + t)*4u; \
    uint32_t a0, a1, a2, a3; \
    asm volatile("ld.shared.b32 %0, [%1];" : "=r"(a0) : "r"(Abuf_r + swz(brow + bcol))); \
    asm volatile("ld.shared.b32 %0, [%1];" : "=r"(a1) : "r"(Abuf_r + swz(brow + 1024u + bcol))); \
    asm volatile("ld.shared.b32 %0, [%1];" : "=r"(a2) : "r"(Abuf_r + swz(brow + bcol + 16u))); \
    asm volatile("ld.shared.b32 %0, [%1];" : "=r"(a3) : "r"(Abuf_r + swz(brow + 1024u + bcol + 16u))); \
    int ub = s*32 + (kc)*8 + t; \
    _Pragma("unroll") for (int nt = 0; nt < 8; nt++) { \
        int nrow = nt*8 + r; \
        uint32_t b0 = B2s[nrow*BPITCH + ub]; \
        uint32_t b1 = B2s[nrow*BPITCH + ub + 4]; \
        mma_tf32(d + nt*4, a0, a1, a2, a3, b0, b1); \
    } \
} while(0)

    float gA[16], gB[16];
#pragma unroll 1
    for (int s = -1; s < 18; s++) {
        int sp = s + 1;
        bool prod = (sp < 18);
        int n = sp >> 1;
        if (prod && (sp & 1) == 0) {
            float offy = __ldg(offp + n*HW);
            float offx = __ldg(offp + (9+n)*HW);
            float mm   = __ldg(offp + (18+n)*HW);
            int ty = n / 3, tx = n - 3*ty;
            float py = (float)(y + ty) + offy;
            float px = (float)(xx + tx) + offx;
            float fy = floorf(py), fx = floorf(px);
            float qy0 = fminf(fmaxf(fy,       0.f), 193.f);
            float qy1 = fminf(fmaxf(fy + 1.f, 0.f), 193.f);
            float qx0 = fminf(fmaxf(fx,       0.f), 193.f);
            float qx1 = fminf(fmaxf(fx + 1.f, 0.f), 193.f);
            float pyc = fminf(fmaxf(py, 0.f), 193.f);
            float pxc = fminf(fmaxf(px, 0.f), 193.f);
            float wy0 = 1.f + (qy0 - pyc), wy1 = 1.f - (qy1 - pyc);
            float wx0 = 1.f + (qx0 - pxc), wx1 = 1.f - (qx1 - pxc);
            int iy0 = (int)qy0, iy1 = (int)qy1, ix0 = (int)qx0, ix1 = (int)qx1;
            bool vy0 = (iy0 >= 1) && (iy0 <= 192);
            bool vy1 = (iy1 >= 1) && (iy1 <= 192);
            bool vx0 = (ix0 >= 1) && (ix0 <= 192);
            bool vx1 = (ix1 >= 1) && (ix1 <= 192);
            cw0 = (vy0 && vx0) ? wy0*wx0*mm : 0.f;
            cw1 = (vy0 && vx1) ? wy0*wx1*mm : 0.f;
            cw2 = (vy1 && vx0) ? wy1*wx0*mm : 0.f;
            cw3 = (vy1 && vx1) ? wy1*wx1*mm : 0.f;
            int jy0 = min(max(iy0, 1), 192) - 1;
            int jy1 = min(max(iy1, 1), 192) - 1;
            int jx0 = min(max(ix0, 1), 192) - 1;
            int jx1 = min(max(ix1, 1), 192) - 1;
            p0 = xb + (jy0*WW + jx0); p1 = xb + (jy0*WW + jx1);
            p2 = xb + (jy1*WW + jx0); p3 = xb + (jy1*WW + jx1);
        }
        int chalf = (sp & 1) * 32;
        uint32_t Abuf_w = AbaseS + (uint32_t)((sp & 1) * SMEM_A);
        uint32_t Abuf_r = AbaseS + (uint32_t)((s & 1) * SMEM_A);

        if (prod) PREF2(gA, 0);
        if (s >= 0) MMACH2(0);
        if (prod) { PREF2(gB, 1); COMB2(gA, 0); }
        if (s >= 0) MMACH2(1);
        if (prod) { PREF2(gA, 2); COMB2(gB, 1); }
        if (s >= 0) MMACH2(2);
        if (prod) { PREF2(gB, 3); COMB2(gA, 2); }
        if (s >= 0) MMACH2(3);
        if (prod) COMB2(gB, 3);
        __syncthreads();
    }

    // writeout D
    float* op = g_mid + (size_t)b*COUT*HW + (rembase + w*16);
#pragma unroll
    for (int nt = 0; nt < 8; nt++) {
        int o0 = nt*8 + 2*t;
        op[(size_t)o0*HW     + r    ] = d[nt*4+0];
        op[(size_t)(o0+1)*HW + r    ] = d[nt*4+1];
        op[(size_t)o0*HW     + r + 8] = d[nt*4+2];
        op[(size_t)(o0+1)*HW + r + 8] = d[nt*4+3];
    }

    // fused BN partial stats (deterministic): reuse A region as reduction pad
    float* red = (float*)(smraw + SMEM_B2);   // 16 warps x 64 ch x 2
#pragma unroll
    for (int nt = 0; nt < 8; nt++) {
#pragma unroll
        for (int e = 0; e < 2; e++) {
            float v0 = d[nt*4 + e], v1 = d[nt*4 + 2 + e];
            float sm = v0 + v1, sq = v0*v0 + v1*v1;
#pragma unroll
            for (int o = 4; o <= 16; o <<= 1) {
                sm += __shfl_xor_sync(0xffffffffu, sm, o);
                sq += __shfl_xor_sync(0xffffffffu, sq, o);
            }
            if (r == 0) {
                int o = nt*8 + 2*t + e;
                red[(w*64 + o)*2]     = sm;
                red[(w*64 + o)*2 + 1] = sq;
            }
        }
    }
    __syncthreads();
    if (tid < 64) {
        float sm = 0.f, sq = 0.f;
#pragma unroll
        for (int wi = 0; wi < 16; wi++) {
            sm += red[(wi*64 + tid)*2];
            sq += red[(wi*64 + tid)*2 + 1];
        }
        g_part[tile*128 + tid*2]     = sm;
        g_part[tile*128 + tid*2 + 1] = sq;
    }
}

// ---------------------------------------------------------------------------
// K4: finalize BN stats from per-tile partials (deterministic)
// ---------------------------------------------------------------------------
__global__ void k4_finalize(const float* __restrict__ gamma,
                            const float* __restrict__ beta) {
    __shared__ float ssm[256], ssq[256];
    int tid = threadIdx.x;
    int c = tid & 63, g4 = tid >> 6;
    float sm = 0.f, sq = 0.f;
    for (int tt = g4*144; tt < (g4+1)*144; tt++) {
        sm += g_part[tt*128 + c*2];
        sq += g_part[tt*128 + c*2 + 1];
    }
    ssm[tid] = sm; ssq[tid] = sq;
    __syncthreads();
    if (tid < 64) {
        float S = ssm[tid] + ssm[tid+64] + ssm[tid+128] + ssm[tid+192];
        float Q = ssq[tid] + ssq[tid+64] + ssq[tid+128] + ssq[tid+192];
        const float inv = 1.f / (float)PIX;
        float mu  = S * inv;
        float var = Q * inv - mu*mu;
        float sc  = __ldg(gamma + tid) * rsqrtf(var + 1e-5f);
        g_scale[tid] = sc;
        g_shift[tid] = __ldg(beta + tid) - mu * sc;
    }
}

// ---------------------------------------------------------------------------
// K5: BN affine + ReLU + 2x2 maxpool
// ---------------------------------------------------------------------------
__global__ void k5_pool(float* __restrict__ out) {
    int idx = blockIdx.x * 256 + threadIdx.x;
    if (idx >= BATCH*COUT*96*96) return;
    int xo = idx % 96;
    int yo = (idx / 96) % 96;
    int c  = (idx / (96*96)) % COUT;
    int b  = idx / (96*96*COUT);
    float sc = g_scale[c], sh = g_shift[c];
    const float* ip = g_mid + ((size_t)(b*COUT + c))*HW + (2*yo)*WW + 2*xo;
    float v0 = fmaxf(fmaf(ip[0],    sc, sh), 0.f);
    float v1 = fmaxf(fmaf(ip[1],    sc, sh), 0.f);
    float v2 = fmaxf(fmaf(ip[WW],   sc, sh), 0.f);
    float v3 = fmaxf(fmaf(ip[WW+1], sc, sh), 0.f);
    out[idx] = fmaxf(fmaxf(v0, v1), fmaxf(v2, v3));
}

// ---------------------------------------------------------------------------
extern "C" void kernel_launch(void* const* d_in, const int* in_sizes, int n_in,
                              void* d_out, int out_size) {
    const float* x     = (const float*)d_in[0];
    const float* wp    = (const float*)d_in[1];
    const float* bp    = (const float*)d_in[2];
    const float* wm    = (const float*)d_in[3];
    const float* bm    = (const float*)d_in[4];
    const float* wc    = (const float*)d_in[5];
    const float* gamma = (const float*)d_in[6];
    const float* beta  = (const float*)d_in[7];
    float* out = (float*)d_out;

    cudaFuncSetAttribute(k1_mma, cudaFuncAttributeMaxDynamicSharedMemorySize, SMEM_K1);
    cudaFuncSetAttribute(k2_mma, cudaFuncAttributeMaxDynamicSharedMemorySize, SMEM_K2);

    k0_prep<<<(64*BPITCH + 255)/256, 256>>>(wp, wm, wc);
    k1_mma<<<NTILE2, 512, SMEM_K1>>>(x, bp, bm);
    k2_mma<<<NTILE2, 512, SMEM_K2>>>(x);
    k4_finalize<<<1, 256>>>(gamma, beta);
    k5_pool<<<(BATCH*COUT*96*96 + 255)/256, 256>>>(out);
}

// round 13
// speedup vs baseline: 1.0170x; 1.0170x over previous
#include <cuda_runtime.h>
#include <math.h>
#include <stdint.h>

#define BATCH 4
#define CIN 64
#define COUT 64
#define HH 192
#define WW 192
#define HW (HH*WW)          // 36864
#define CHW (CIN*HW)
#define PIX (BATCH*HW)      // 147456
#define KROWS 576
#define NTILE2 (PIX/256)    // 576 tiles of 256 pixels
#define BPITCH 580          // B row pitch in u32 (576 + 4 pad)
#define SMEM_A  (256*32*4)               // 32 KB per A stage
#define SMEM_B2 (64*BPITCH*4)            // 148480
#define SMEM_B1 (32*BPITCH*4)            // 74240
#define SMEM_K2 (SMEM_B2 + 2*SMEM_A)     // 214016
#define SMEM_K1 (SMEM_B1 + 2*SMEM_A)     // 139776

__device__ __forceinline__ uint32_t smem_u32(const void* p) {
    uint32_t a;
    asm("{ .reg .u64 t; cvta.to.shared.u64 t, %1; cvt.u32.u64 %0, t; }" : "=r"(a) : "l"(p));
    return a;
}
__device__ __forceinline__ uint32_t tf32cvt(float f) {
    uint32_t u; asm("cvt.rna.tf32.f32 %0, %1;" : "=r"(u) : "f"(f)); return u;
}
__device__ __forceinline__ void mma_tf32(float* d, uint32_t a0, uint32_t a1,
                                         uint32_t a2, uint32_t a3,
                                         uint32_t b0, uint32_t b1) {
    asm volatile(
        "mma.sync.aligned.m16n8k8.row.col.f32.tf32.tf32.f32 "
        "{%0,%1,%2,%3}, {%4,%5,%6,%7}, {%8,%9}, {%0,%1,%2,%3};"
        : "+f"(d[0]), "+f"(d[1]), "+f"(d[2]), "+f"(d[3])
        : "r"(a0), "r"(a1), "r"(a2), "r"(a3), "r"(b0), "r"(b1));
}
__device__ __forceinline__ uint32_t swz(uint32_t byte) {
    return byte ^ ((byte >> 3) & 0x70u);
}

// ---- scratch (device globals) ----
__device__ uint32_t g_wB1[32*BPITCH];
__device__ uint32_t g_wB2[64*BPITCH];
__device__ float    g_off[BATCH*27*HW];
__device__ float    g_mid[BATCH*COUT*HW];
__device__ float    g_part[NTILE2*128];    // per-tile [64ch][sum,sq]
__device__ float    g_scale[COUT];
__device__ float    g_shift[COUT];

// ---------------------------------------------------------------------------
// K0: pack tf32 weight matrices
// ---------------------------------------------------------------------------
__global__ void k0_prep(const float* __restrict__ wp, const float* __restrict__ wm,
                        const float* __restrict__ wc) {
    int i = blockIdx.x * 256 + threadIdx.x;
    if (i < 32*BPITCH) {
        int n = i / BPITCH, u = i - n*BPITCH;
        uint32_t val = 0;
        if (u < 576 && n < 27) {
            int tap = u >> 6, c = u & 63;
            float w = (n < 18) ? wp[n*KROWS + c*9 + tap] : wm[(n-18)*KROWS + c*9 + tap];
            val = tf32cvt(w);
        }
        g_wB1[i] = val;
    }
    if (i < 64*BPITCH) {
        int n = i / BPITCH, u = i - n*BPITCH;
        uint32_t val = 0;
        if (u < 576) {
            int tap = u >> 6, c = u & 63;
            val = tf32cvt(wc[n*KROWS + c*9 + tap]);
        }
        g_wB2[i] = val;
    }
}

// ---------------------------------------------------------------------------
// probe: no-op kernel to steer ncu's capture slot onto k2 (4th launch)
// ---------------------------------------------------------------------------
__global__ void k_probe() {}

// ---------------------------------------------------------------------------
// K1: offset/mask conv as tf32 HMMA GEMM (R9-proven body).
// ---------------------------------------------------------------------------
__global__ void __launch_bounds__(512, 1) k1_mma(const float* __restrict__ x,
                                                 const float* __restrict__ bp,
                                                 const float* __restrict__ bm) {
    extern __shared__ __align__(1024) char smraw[];
    uint32_t* B1s = (uint32_t*)smraw;
    const uint32_t AbaseS = smem_u32(smraw) + SMEM_B1;

    int tid = threadIdx.x;
    {
        const uint4* src = (const uint4*)g_wB1;
        uint4* dst = (uint4*)B1s;
        for (int i = tid; i < (32*BPITCH)/4; i += 512) dst[i] = src[i];
    }
    __syncthreads();

    int tile = blockIdx.x;
    int lp   = tid & 255;
    int uh   = tid >> 8;
    int b    = tile / 144;
    int rembase = (tile - b*144) * 256;
    int rem  = rembase + lp;
    int y    = rem / WW, xx = rem - y*WW;
    const float* xb = x + (size_t)b*CHW;

    int lane = tid & 31, w = tid >> 5;
    int r = lane >> 2, t = lane & 3;

    float d[16];
#pragma unroll
    for (int i = 0; i < 16; i++) d[i] = 0.f;

#pragma unroll 1
    for (int s = -1; s < 18; s++) {
        if (s >= 0) {
            uint32_t Abuf = AbaseS + (uint32_t)((s & 1) * SMEM_A);
#pragma unroll
            for (int kc = 0; kc < 4; kc++) {
                uint32_t brow = (uint32_t)(w*16 + r)*128u;
                uint32_t bcol = (uint32_t)(kc*8 + t)*4u;
                uint32_t a0, a1, a2, a3;
                asm volatile("ld.shared.b32 %0, [%1];" : "=r"(a0) : "r"(Abuf + swz(brow + bcol)));
                asm volatile("ld.shared.b32 %0, [%1];" : "=r"(a1) : "r"(Abuf + swz(brow + 1024u + bcol)));
                asm volatile("ld.shared.b32 %0, [%1];" : "=r"(a2) : "r"(Abuf + swz(brow + bcol + 16u)));
                asm volatile("ld.shared.b32 %0, [%1];" : "=r"(a3) : "r"(Abuf + swz(brow + 1024u + bcol + 16u)));
                int ub = s*32 + kc*8 + t;
#pragma unroll
                for (int nt = 0; nt < 4; nt++) {
                    int nrow = nt*8 + r;
                    uint32_t b0 = B1s[nrow*BPITCH + ub];
                    uint32_t b1 = B1s[nrow*BPITCH + ub + 4];
                    mma_tf32(d + nt*4, a0, a1, a2, a3, b0, b1);
                }
            }
        }
        int sp = s + 1;
        if (sp < 18) {
            int n  = sp >> 1;
            int ty = n / 3, tx = n - 3*ty;
            int iy = y + ty - 1, ix = xx + tx - 1;
            bool valid = (iy >= 0) && (iy < HH) && (ix >= 0) && (ix < WW);
            int chalf = (sp & 1) * 32;
            uint32_t Abuf = AbaseS + (uint32_t)((sp & 1) * SMEM_A);
            const float* xs = xb + iy*WW + ix;
#pragma unroll
            for (int q = 0; q < 4; q++) {
                uint32_t v[4];
#pragma unroll
                for (int ci = 0; ci < 4; ci++) {
                    int c = chalf + uh*16 + q*4 + ci;
                    float sv = valid ? __ldg(xs + (size_t)c*HW) : 0.f;
                    v[ci] = tf32cvt(sv);
                }
                uint32_t byte = swz((uint32_t)lp*128u + (uint32_t)(uh*16 + q*4)*4u);
                asm volatile("st.shared.v4.b32 [%0], {%1,%2,%3,%4};"
                    :: "r"(Abuf + byte), "r"(v[0]), "r"(v[1]), "r"(v[2]), "r"(v[3])
                    : "memory");
            }
        }
        __syncthreads();
    }

    float* op = g_off + (size_t)b*27*HW + (rembase + w*16);
#pragma unroll
    for (int nt = 0; nt < 4; nt++) {
#pragma unroll
        for (int e = 0; e < 2; e++) {
            int o = nt*8 + 2*t + e;
            if (o >= 27) continue;
            float add = (o < 18) ? __ldg(bp + o) : __ldg(bm + o - 18);
            float v0 = d[nt*4 + e]     + add;
            float v1 = d[nt*4 + 2 + e] + add;
            if (o >= 18) {
                v0 = 1.f / (1.f + expf(-v0));
                v1 = 1.f / (1.f + expf(-v1));
            }
            op[(size_t)o*HW + r]     = v0;
            op[(size_t)o*HW + r + 8] = v1;
        }
    }
}

// ---------------------------------------------------------------------------
// K2: deformable sampling + main conv as tf32 HMMA GEMM (R9-proven body)
//     + fused per-tile BN partial statistics in the epilogue.
// ---------------------------------------------------------------------------
__global__ void __launch_bounds__(512, 1) k2_mma(const float* __restrict__ x) {
    extern __shared__ __align__(1024) char smraw[];
    uint32_t* B2s = (uint32_t*)smraw;
    const uint32_t AbaseS = smem_u32(smraw) + SMEM_B2;

    int tid = threadIdx.x;
    {
        const uint4* src = (const uint4*)g_wB2;
        uint4* dst = (uint4*)B2s;
        for (int i = tid; i < (64*BPITCH)/4; i += 512) dst[i] = src[i];
    }
    __syncthreads();

    int tile = blockIdx.x;
    int lp   = tid & 255;
    int uh   = tid >> 8;
    int b    = tile / 144;
    int rembase = (tile - b*144) * 256;
    int rem  = rembase + lp;
    int y    = rem / WW, xx = rem - y*WW;
    const float* xb   = x + (size_t)b*CHW;
    const float* offp = g_off + (size_t)b*27*HW + rem;

    int lane = tid & 31, w = tid >> 5;
    int r = lane >> 2, t = lane & 3;

    float d[32];
#pragma unroll
    for (int i = 0; i < 32; i++) d[i] = 0.f;

    float cw0=0, cw1=0, cw2=0, cw3=0;
    int   co0=0, co1=0, co2=0, co3=0;

#pragma unroll 1
    for (int s = -1; s < 18; s++) {
        if (s >= 0) {
            uint32_t Abuf = AbaseS + (uint32_t)((s & 1) * SMEM_A);
#pragma unroll
            for (int kc = 0; kc < 4; kc++) {
                uint32_t brow = (uint32_t)(w*16 + r)*128u;
                uint32_t bcol = (uint32_t)(kc*8 + t)*4u;
                uint32_t a0, a1, a2, a3;
                asm volatile("ld.shared.b32 %0, [%1];" : "=r"(a0) : "r"(Abuf + swz(brow + bcol)));
                asm volatile("ld.shared.b32 %0, [%1];" : "=r"(a1) : "r"(Abuf + swz(brow + 1024u + bcol)));
                asm volatile("ld.shared.b32 %0, [%1];" : "=r"(a2) : "r"(Abuf + swz(brow + bcol + 16u)));
                asm volatile("ld.shared.b32 %0, [%1];" : "=r"(a3) : "r"(Abuf + swz(brow + 1024u + bcol + 16u)));
                int ub = s*32 + kc*8 + t;
#pragma unroll
                for (int nt = 0; nt < 8; nt++) {
                    int nrow = nt*8 + r;
                    uint32_t b0 = B2s[nrow*BPITCH + ub];
                    uint32_t b1 = B2s[nrow*BPITCH + ub + 4];
                    mma_tf32(d + nt*4, a0, a1, a2, a3, b0, b1);
                }
            }
        }
        int sp = s + 1;
        if (sp < 18) {
            int n = sp >> 1;
            if ((sp & 1) == 0) {   // new tap: recompute bilinear corners
                float offy = __ldg(offp + n*HW);
                float offx = __ldg(offp + (9+n)*HW);
                float mm   = __ldg(offp + (18+n)*HW);
                int ty = n / 3, tx = n - 3*ty;
                float py = (float)(y + ty) + offy;
                float px = (float)(xx + tx) + offx;
                float fy = floorf(py), fx = floorf(px);
                float qy0 = fminf(fmaxf(fy,       0.f), 193.f);
                float qy1 = fminf(fmaxf(fy + 1.f, 0.f), 193.f);
                float qx0 = fminf(fmaxf(fx,       0.f), 193.f);
                float qx1 = fminf(fmaxf(fx + 1.f, 0.f), 193.f);
                float pyc = fminf(fmaxf(py, 0.f), 193.f);
                float pxc = fminf(fmaxf(px, 0.f), 193.f);
                float wy0 = 1.f + (qy0 - pyc), wy1 = 1.f - (qy1 - pyc);
                float wx0 = 1.f + (qx0 - pxc), wx1 = 1.f - (qx1 - pxc);
                int iy0 = (int)qy0, iy1 = (int)qy1, ix0 = (int)qx0, ix1 = (int)qx1;
                bool vy0 = (iy0 >= 1) && (iy0 <= 192);
                bool vy1 = (iy1 >= 1) && (iy1 <= 192);
                bool vx0 = (ix0 >= 1) && (ix0 <= 192);
                bool vx1 = (ix1 >= 1) && (ix1 <= 192);
                cw0 = (vy0 && vx0) ? wy0*wx0*mm : 0.f;
                cw1 = (vy0 && vx1) ? wy0*wx1*mm : 0.f;
                cw2 = (vy1 && vx0) ? wy1*wx0*mm : 0.f;
                cw3 = (vy1 && vx1) ? wy1*wx1*mm : 0.f;
                int jy0 = min(max(iy0, 1), 192) - 1;
                int jy1 = min(max(iy1, 1), 192) - 1;
                int jx0 = min(max(ix0, 1), 192) - 1;
                int jx1 = min(max(ix1, 1), 192) - 1;
                co0 = jy0*WW + jx0; co1 = jy0*WW + jx1;
                co2 = jy1*WW + jx0; co3 = jy1*WW + jx1;
            }
            int chalf = (sp & 1) * 32;
            uint32_t Abuf = AbaseS + (uint32_t)((sp & 1) * SMEM_A);
#pragma unroll
            for (int q = 0; q < 4; q++) {
                uint32_t v[4];
#pragma unroll
                for (int ci = 0; ci < 4; ci++) {
                    int c = chalf + uh*16 + q*4 + ci;
                    const float* xc = xb + (size_t)c*HW;
                    float sv = cw0*__ldg(xc + co0) + cw1*__ldg(xc + co1)
                             + cw2*__ldg(xc + co2) + cw3*__ldg(xc + co3);
                    v[ci] = tf32cvt(sv);
                }
                uint32_t byte = swz((uint32_t)lp*128u + (uint32_t)(uh*16 + q*4)*4u);
                asm volatile("st.shared.v4.b32 [%0], {%1,%2,%3,%4};"
                    :: "r"(Abuf + byte), "r"(v[0]), "r"(v[1]), "r"(v[2]), "r"(v[3])
                    : "memory");
            }
        }
        __syncthreads();
    }

    // writeout D: warp w owns pixels rembase + w*16 + {r, r+8}
    float* op = g_mid + (size_t)b*COUT*HW + (rembase + w*16);
#pragma unroll
    for (int nt = 0; nt < 8; nt++) {
        int o0 = nt*8 + 2*t;
        op[(size_t)o0*HW     + r    ] = d[nt*4+0];
        op[(size_t)(o0+1)*HW + r    ] = d[nt*4+1];
        op[(size_t)o0*HW     + r + 8] = d[nt*4+2];
        op[(size_t)(o0+1)*HW + r + 8] = d[nt*4+3];
    }

    // fused BN partial stats (deterministic): reuse A region as reduction pad
    float* red = (float*)(smraw + SMEM_B2);   // 16 warps x 64 ch x 2
#pragma unroll
    for (int nt = 0; nt < 8; nt++) {
#pragma unroll
        for (int e = 0; e < 2; e++) {
            float v0 = d[nt*4 + e], v1 = d[nt*4 + 2 + e];
            float sm = v0 + v1, sq = v0*v0 + v1*v1;
#pragma unroll
            for (int o = 4; o <= 16; o <<= 1) {
                sm += __shfl_xor_sync(0xffffffffu, sm, o);
                sq += __shfl_xor_sync(0xffffffffu, sq, o);
            }
            if (r == 0) {
                int o = nt*8 + 2*t + e;
                red[(w*64 + o)*2]     = sm;
                red[(w*64 + o)*2 + 1] = sq;
            }
        }
    }
    __syncthreads();
    if (tid < 64) {
        float sm = 0.f, sq = 0.f;
#pragma unroll
        for (int wi = 0; wi < 16; wi++) {
            sm += red[(wi*64 + tid)*2];
            sq += red[(wi*64 + tid)*2 + 1];
        }
        g_part[tile*128 + tid*2]     = sm;
        g_part[tile*128 + tid*2 + 1] = sq;
    }
}

// ---------------------------------------------------------------------------
// K4: finalize BN stats — parallel: one block per channel, 256 threads
// ---------------------------------------------------------------------------
__global__ void k4_finalize(const float* __restrict__ gamma,
                            const float* __restrict__ beta) {
    __shared__ float ssm[256], ssq[256];
    int c = blockIdx.x;
    int tid = threadIdx.x;
    float sm = 0.f, sq = 0.f;
    for (int tt = tid; tt < NTILE2; tt += 256) {
        sm += g_part[tt*128 + c*2];
        sq += g_part[tt*128 + c*2 + 1];
    }
    ssm[tid] = sm; ssq[tid] = sq;
    __syncthreads();
    for (int st = 128; st > 0; st >>= 1) {
        if (tid < st) { ssm[tid] += ssm[tid+st]; ssq[tid] += ssq[tid+st]; }
        __syncthreads();
    }
    if (tid == 0) {
        const float inv = 1.f / (float)PIX;
        float mu  = ssm[0] * inv;
        float var = ssq[0] * inv - mu*mu;
        float sc  = __ldg(gamma + c) * rsqrtf(var + 1e-5f);
        g_scale[c] = sc;
        g_shift[c] = __ldg(beta + c) - mu * sc;
    }
}

// ---------------------------------------------------------------------------
// K5: BN affine + ReLU + 2x2 maxpool
// ---------------------------------------------------------------------------
__global__ void k5_pool(float* __restrict__ out) {
    int idx = blockIdx.x * 256 + threadIdx.x;
    if (idx >= BATCH*COUT*96*96) return;
    int xo = idx % 96;
    int yo = (idx / 96) % 96;
    int c  = (idx / (96*96)) % COUT;
    int b  = idx / (96*96*COUT);
    float sc = g_scale[c], sh = g_shift[c];
    const float* ip = g_mid + ((size_t)(b*COUT + c))*HW + (2*yo)*WW + 2*xo;
    float v0 = fmaxf(fmaf(ip[0],    sc, sh), 0.f);
    float v1 = fmaxf(fmaf(ip[1],    sc, sh), 0.f);
    float v2 = fmaxf(fmaf(ip[WW],   sc, sh), 0.f);
    float v3 = fmaxf(fmaf(ip[WW+1], sc, sh), 0.f);
    out[idx] = fmaxf(fmaxf(v0, v1), fmaxf(v2, v3));
}

// ---------------------------------------------------------------------------
extern "C" void kernel_launch(void* const* d_in, const int* in_sizes, int n_in,
                              void* d_out, int out_size) {
    const float* x     = (const float*)d_in[0];
    const float* wp    = (const float*)d_in[1];
    const float* bp    = (const float*)d_in[2];
    const float* wm    = (const float*)d_in[3];
    const float* bm    = (const float*)d_in[4];
    const float* wc    = (const float*)d_in[5];
    const float* gamma = (const float*)d_in[6];
    const float* beta  = (const float*)d_in[7];
    float* out = (float*)d_out;

    cudaFuncSetAttribute(k1_mma, cudaFuncAttributeMaxDynamicSharedMemorySize, SMEM_K1);
    cudaFuncSetAttribute(k2_mma, cudaFuncAttributeMaxDynamicSharedMemorySize, SMEM_K2);

    k0_prep<<<(64*BPITCH + 255)/256, 256>>>(wp, wm, wc);
    k1_mma<<<NTILE2, 512, SMEM_K1>>>(x, bp, bm);
    k_probe<<<1, 32>>>();   // position k2 at launch slot 4 for the ncu capture
    k2_mma<<<NTILE2, 512, SMEM_K2>>>(x);
    k4_finalize<<<64, 256>>>(gamma, beta);
    k5_pool<<<(BATCH*COUT*96*96 + 255)/256, 256>>>(out);
}

// round 14
// speedup vs baseline: 1.1881x; 1.1683x over previous
#include <cuda_runtime.h>
#include <math.h>
#include <stdint.h>

#define BATCH 4
#define CIN 64
#define COUT 64
#define HH 192
#define WW 192
#define HW (HH*WW)          // 36864
#define CHW (CIN*HW)
#define PIX (BATCH*HW)      // 147456
#define KROWS 576
#define NT (PIX/128)        // 1152 tiles of 128 pixels
#define TPB 288             // tiles per batch image
#define SMEM_A (128*32*4)   // 16384 per A stage
#define BCH2 (64*36*4)      // 9216  per B chunk (k2), pitch 36 u32
#define BCH1 (32*36*4)      // 4608  per B chunk (k1)
#define SMEM_K2 (2*SMEM_A + 2*BCH2)   // 51200
#define SMEM_K1 (2*SMEM_A + 2*BCH1)   // 41984

__device__ __forceinline__ uint32_t smem_u32(const void* p) {
    uint32_t a;
    asm("{ .reg .u64 t; cvta.to.shared.u64 t, %1; cvt.u32.u64 %0, t; }" : "=r"(a) : "l"(p));
    return a;
}
__device__ __forceinline__ uint32_t tf32cvt(float f) {
    uint32_t u; asm("cvt.rna.tf32.f32 %0, %1;" : "=r"(u) : "f"(f)); return u;
}
__device__ __forceinline__ void mma_tf32(float* d, uint32_t a0, uint32_t a1,
                                         uint32_t a2, uint32_t a3,
                                         uint32_t b0, uint32_t b1) {
    asm volatile(
        "mma.sync.aligned.m16n8k8.row.col.f32.tf32.tf32.f32 "
        "{%0,%1,%2,%3}, {%4,%5,%6,%7}, {%8,%9}, {%0,%1,%2,%3};"
        : "+f"(d[0]), "+f"(d[1]), "+f"(d[2]), "+f"(d[3])
        : "r"(a0), "r"(a1), "r"(a2), "r"(a3), "r"(b0), "r"(b1));
}
__device__ __forceinline__ uint32_t swz(uint32_t byte) {
    return byte ^ ((byte >> 3) & 0x70u);
}

// ---- scratch (device globals) ----
__device__ uint32_t g_wB1c[18*1024];   // k1 B chunks: [s][n(32)][ubl(32)] tf32
__device__ uint32_t g_wB2c[18*2048];   // k2 B chunks: [s][n(64)][ubl(32)] tf32
__device__ float    g_off[BATCH*27*HW];
__device__ float    g_mid[BATCH*COUT*HW];
__device__ float    g_part[NT*128];    // per-tile [64ch][sum,sq]
__device__ float    g_scale[COUT];
__device__ float    g_shift[COUT];

// ---------------------------------------------------------------------------
// K0: pack tf32 weight chunk matrices
// ---------------------------------------------------------------------------
__global__ void k0_prep(const float* __restrict__ wp, const float* __restrict__ wm,
                        const float* __restrict__ wc) {
    int i = blockIdx.x * 256 + threadIdx.x;
    if (i < 18*1024) {
        int s = i >> 10, r = i & 1023;
        int n = r >> 5, ubl = r & 31;
        uint32_t val = 0;
        if (n < 27) {
            int u = s*32 + ubl;
            int tap = u >> 6, c = u & 63;
            float w = (n < 18) ? wp[n*KROWS + c*9 + tap] : wm[(n-18)*KROWS + c*9 + tap];
            val = tf32cvt(w);
        }
        g_wB1c[i] = val;
    }
    if (i < 18*2048) {
        int s = i >> 11, r = i & 2047;
        int n = r >> 5, ubl = r & 31;
        int u = s*32 + ubl;
        int tap = u >> 6, c = u & 63;
        g_wB2c[i] = tf32cvt(wc[n*KROWS + c*9 + tap]);
    }
}

__global__ void k_probe() {}

// ---------------------------------------------------------------------------
// K1: offset/mask conv as tf32 HMMA GEMM, M=128 tile, streamed B chunks.
// ---------------------------------------------------------------------------
__global__ void __launch_bounds__(256, 2) k1_mma(const float* __restrict__ x,
                                                 const float* __restrict__ bp,
                                                 const float* __restrict__ bm) {
    extern __shared__ __align__(1024) char smraw[];
    uint32_t* Bsm = (uint32_t*)smraw;                  // 2 x BCH1
    const uint32_t AbaseS = smem_u32(smraw) + 2*BCH1;

    int tid = threadIdx.x;
    int tile = blockIdx.x;
    int lp   = tid & 127;
    int uh   = tid >> 7;
    int b    = tile / TPB;
    int rembase = (tile - b*TPB) * 128;
    int rem  = rembase + lp;
    int y    = rem / WW, xx = rem - y*WW;
    const float* xb = x + (size_t)b*CHW;

    int lane = tid & 31, w = tid >> 5;
    int r = lane >> 2, t = lane & 3;

    // preload B chunk 0
    {
        const uint4* src = (const uint4*)(g_wB1c);
        uint4 v0 = src[tid];
        ((uint4*)0, 0);
        int j = tid;          // 256 uint4 = 1024 u32
        int n = j >> 3, ubl = (j & 7) * 4;
        uint32_t byte = (uint32_t)(n*36 + ubl)*4u;
        asm volatile("st.shared.v4.b32 [%0], {%1,%2,%3,%4};"
            :: "r"(smem_u32(smraw) + byte), "r"(v0.x), "r"(v0.y), "r"(v0.z), "r"(v0.w)
            : "memory");
    }

    float d[16];
#pragma unroll
    for (int i = 0; i < 16; i++) d[i] = 0.f;

#pragma unroll 1
    for (int s = -1; s < 18; s++) {
        int sp = s + 1;
        // prefetch B chunk sp (issue LDG early)
        uint4 bch; bool doB = (sp < 18 && sp > 0);
        if (doB) bch = ((const uint4*)(g_wB2c, g_wB1c + sp*1024))[tid];

        if (s >= 0) {
            uint32_t Abuf = AbaseS + (uint32_t)((s & 1) * SMEM_A);
            const uint32_t* Bs = Bsm + (s & 1) * (BCH1/4);
#pragma unroll
            for (int kc = 0; kc < 4; kc++) {
                uint32_t brow = (uint32_t)(w*16 + r)*128u;
                uint32_t bcol = (uint32_t)(kc*8 + t)*4u;
                uint32_t a0, a1, a2, a3;
                asm volatile("ld.shared.b32 %0, [%1];" : "=r"(a0) : "r"(Abuf + swz(brow + bcol)));
                asm volatile("ld.shared.b32 %0, [%1];" : "=r"(a1) : "r"(Abuf + swz(brow + 1024u + bcol)));
                asm volatile("ld.shared.b32 %0, [%1];" : "=r"(a2) : "r"(Abuf + swz(brow + bcol + 16u)));
                asm volatile("ld.shared.b32 %0, [%1];" : "=r"(a3) : "r"(Abuf + swz(brow + 1024u + bcol + 16u)));
                int ubl = kc*8 + t;
#pragma unroll
                for (int nt = 0; nt < 4; nt++) {
                    int nrow = nt*8 + r;
                    uint32_t b0 = Bs[nrow*36 + ubl];
                    uint32_t b1 = Bs[nrow*36 + ubl + 4];
                    mma_tf32(d + nt*4, a0, a1, a2, a3, b0, b1);
                }
            }
        }
        if (sp < 18) {
            int n  = sp >> 1;
            int ty = n / 3, tx = n - 3*ty;
            int iy = y + ty - 1, ix = xx + tx - 1;
            bool valid = (iy >= 0) && (iy < HH) && (ix >= 0) && (ix < WW);
            int chalf = (sp & 1) * 32;
            uint32_t Abuf = AbaseS + (uint32_t)((sp & 1) * SMEM_A);
            const float* xs = xb + iy*WW + ix;
#pragma unroll
            for (int q = 0; q < 4; q++) {
                uint32_t v[4];
#pragma unroll
                for (int ci = 0; ci < 4; ci++) {
                    int c = chalf + uh*16 + q*4 + ci;
                    float sv = valid ? __ldg(xs + (size_t)c*HW) : 0.f;
                    v[ci] = tf32cvt(sv);
                }
                uint32_t byte = swz((uint32_t)lp*128u + (uint32_t)(uh*16 + q*4)*4u);
                asm volatile("st.shared.v4.b32 [%0], {%1,%2,%3,%4};"
                    :: "r"(Abuf + byte), "r"(v[0]), "r"(v[1]), "r"(v[2]), "r"(v[3])
                    : "memory");
            }
            if (doB) {
                int j = tid;
                int n2 = j >> 3, ubl = (j & 7) * 4;
                uint32_t byte = (uint32_t)((sp & 1) * BCH1) + (uint32_t)(n2*36 + ubl)*4u;
                asm volatile("st.shared.v4.b32 [%0], {%1,%2,%3,%4};"
                    :: "r"(smem_u32(smraw) + byte), "r"(bch.x), "r"(bch.y), "r"(bch.z), "r"(bch.w)
                    : "memory");
            }
        }
        __syncthreads();
    }

    float* op = g_off + (size_t)b*27*HW + (rembase + w*16);
#pragma unroll
    for (int nt = 0; nt < 4; nt++) {
#pragma unroll
        for (int e = 0; e < 2; e++) {
            int o = nt*8 + 2*t + e;
            if (o >= 27) continue;
            float add = (o < 18) ? __ldg(bp + o) : __ldg(bm + o - 18);
            float v0 = d[nt*4 + e]     + add;
            float v1 = d[nt*4 + 2 + e] + add;
            if (o >= 18) {
                v0 = 1.f / (1.f + expf(-v0));
                v1 = 1.f / (1.f + expf(-v1));
            }
            op[(size_t)o*HW + r]     = v0;
            op[(size_t)o*HW + r + 8] = v1;
        }
    }
}

// ---------------------------------------------------------------------------
// K2: deformable sampling + main conv, M=128 tile, streamed B chunks,
//     fused BN partials. 2 CTAs/SM.
// ---------------------------------------------------------------------------
__global__ void __launch_bounds__(256, 2) k2_mma(const float* __restrict__ x) {
    extern __shared__ __align__(1024) char smraw[];
    uint32_t* Bsm = (uint32_t*)smraw;                  // 2 x BCH2
    const uint32_t AbaseS = smem_u32(smraw) + 2*BCH2;

    int tid = threadIdx.x;
    int tile = blockIdx.x;
    int lp   = tid & 127;
    int uh   = tid >> 7;
    int b    = tile / TPB;
    int rembase = (tile - b*TPB) * 128;
    int rem  = rembase + lp;
    int y    = rem / WW, xx = rem - y*WW;
    const float* xb   = x + (size_t)b*CHW;
    const float* offp = g_off + (size_t)b*27*HW + rem;

    int lane = tid & 31, w = tid >> 5;
    int r = lane >> 2, t = lane & 3;

    // preload B chunk 0: 2048 u32 = 512 uint4, 256 threads x 2
    {
        const uint4* src = (const uint4*)g_wB2c;
#pragma unroll
        for (int jj = 0; jj < 2; jj++) {
            int j = tid*2 + jj;
            uint4 v = src[j];
            int n = j >> 3, ubl = (j & 7) * 4;
            uint32_t byte = (uint32_t)(n*36 + ubl)*4u;
            asm volatile("st.shared.v4.b32 [%0], {%1,%2,%3,%4};"
                :: "r"(smem_u32(smraw) + byte), "r"(v.x), "r"(v.y), "r"(v.z), "r"(v.w)
                : "memory");
        }
    }

    float d[32];
#pragma unroll
    for (int i = 0; i < 32; i++) d[i] = 0.f;

    float cw0=0, cw1=0, cw2=0, cw3=0;
    int   co0=0, co1=0, co2=0, co3=0;

#pragma unroll 1
    for (int s = -1; s < 18; s++) {
        int sp = s + 1;
        uint4 bch0, bch1; bool doB = (sp < 18 && sp > 0);
        if (doB) {
            const uint4* src = (const uint4*)(g_wB2c + sp*2048);
            bch0 = src[tid*2];
            bch1 = src[tid*2 + 1];
        }

        if (s >= 0) {
            uint32_t Abuf = AbaseS + (uint32_t)((s & 1) * SMEM_A);
            const uint32_t* Bs = Bsm + (s & 1) * (BCH2/4);
#pragma unroll
            for (int kc = 0; kc < 4; kc++) {
                uint32_t brow = (uint32_t)(w*16 + r)*128u;
                uint32_t bcol = (uint32_t)(kc*8 + t)*4u;
                uint32_t a0, a1, a2, a3;
                asm volatile("ld.shared.b32 %0, [%1];" : "=r"(a0) : "r"(Abuf + swz(brow + bcol)));
                asm volatile("ld.shared.b32 %0, [%1];" : "=r"(a1) : "r"(Abuf + swz(brow + 1024u + bcol)));
                asm volatile("ld.shared.b32 %0, [%1];" : "=r"(a2) : "r"(Abuf + swz(brow + bcol + 16u)));
                asm volatile("ld.shared.b32 %0, [%1];" : "=r"(a3) : "r"(Abuf + swz(brow + 1024u + bcol + 16u)));
                int ubl = kc*8 + t;
#pragma unroll
                for (int nt = 0; nt < 8; nt++) {
                    int nrow = nt*8 + r;
                    uint32_t b0 = Bs[nrow*36 + ubl];
                    uint32_t b1 = Bs[nrow*36 + ubl + 4];
                    mma_tf32(d + nt*4, a0, a1, a2, a3, b0, b1);
                }
            }
        }
        if (sp < 18) {
            int n = sp >> 1;
            if ((sp & 1) == 0) {   // new tap: recompute bilinear corners
                float offy = __ldg(offp + n*HW);
                float offx = __ldg(offp + (9+n)*HW);
                float mm   = __ldg(offp + (18+n)*HW);
                int ty = n / 3, tx = n - 3*ty;
                float py = (float)(y + ty) + offy;
                float px = (float)(xx + tx) + offx;
                float fy = floorf(py), fx = floorf(px);
                float qy0 = fminf(fmaxf(fy,       0.f), 193.f);
                float qy1 = fminf(fmaxf(fy + 1.f, 0.f), 193.f);
                float qx0 = fminf(fmaxf(fx,       0.f), 193.f);
                float qx1 = fminf(fmaxf(fx + 1.f, 0.f), 193.f);
                float pyc = fminf(fmaxf(py, 0.f), 193.f);
                float pxc = fminf(fmaxf(px, 0.f), 193.f);
                float wy0 = 1.f + (qy0 - pyc), wy1 = 1.f - (qy1 - pyc);
                float wx0 = 1.f + (qx0 - pxc), wx1 = 1.f - (qx1 - pxc);
                int iy0 = (int)qy0, iy1 = (int)qy1, ix0 = (int)qx0, ix1 = (int)qx1;
                bool vy0 = (iy0 >= 1) && (iy0 <= 192);
                bool vy1 = (iy1 >= 1) && (iy1 <= 192);
                bool vx0 = (ix0 >= 1) && (ix0 <= 192);
                bool vx1 = (ix1 >= 1) && (ix1 <= 192);
                cw0 = (vy0 && vx0) ? wy0*wx0*mm : 0.f;
                cw1 = (vy0 && vx1) ? wy0*wx1*mm : 0.f;
                cw2 = (vy1 && vx0) ? wy1*wx0*mm : 0.f;
                cw3 = (vy1 && vx1) ? wy1*wx1*mm : 0.f;
                int jy0 = min(max(iy0, 1), 192) - 1;
                int jy1 = min(max(iy1, 1), 192) - 1;
                int jx0 = min(max(ix0, 1), 192) - 1;
                int jx1 = min(max(ix1, 1), 192) - 1;
                co0 = jy0*WW + jx0; co1 = jy0*WW + jx1;
                co2 = jy1*WW + jx0; co3 = jy1*WW + jx1;
            }
            int chalf = (sp & 1) * 32;
            uint32_t Abuf = AbaseS + (uint32_t)((sp & 1) * SMEM_A);
#pragma unroll
            for (int q = 0; q < 4; q++) {
                uint32_t v[4];
#pragma unroll
                for (int ci = 0; ci < 4; ci++) {
                    int c = chalf + uh*16 + q*4 + ci;
                    const float* xc = xb + (size_t)c*HW;
                    float sv = cw0*__ldg(xc + co0) + cw1*__ldg(xc + co1)
                             + cw2*__ldg(xc + co2) + cw3*__ldg(xc + co3);
                    v[ci] = tf32cvt(sv);
                }
                uint32_t byte = swz((uint32_t)lp*128u + (uint32_t)(uh*16 + q*4)*4u);
                asm volatile("st.shared.v4.b32 [%0], {%1,%2,%3,%4};"
                    :: "r"(Abuf + byte), "r"(v[0]), "r"(v[1]), "r"(v[2]), "r"(v[3])
                    : "memory");
            }
            if (doB) {
#pragma unroll
                for (int jj = 0; jj < 2; jj++) {
                    int j = tid*2 + jj;
                    uint4 v = jj ? bch1 : bch0;
                    int n2 = j >> 3, ubl = (j & 7) * 4;
                    uint32_t byte = (uint32_t)((sp & 1) * BCH2) + (uint32_t)(n2*36 + ubl)*4u;
                    asm volatile("st.shared.v4.b32 [%0], {%1,%2,%3,%4};"
                        :: "r"(smem_u32(smraw) + byte), "r"(v.x), "r"(v.y), "r"(v.z), "r"(v.w)
                        : "memory");
                }
            }
        }
        __syncthreads();
    }

    // writeout D: warp w owns pixels rembase + w*16 + {r, r+8}
    float* op = g_mid + (size_t)b*COUT*HW + (rembase + w*16);
#pragma unroll
    for (int nt = 0; nt < 8; nt++) {
        int o0 = nt*8 + 2*t;
        op[(size_t)o0*HW     + r    ] = d[nt*4+0];
        op[(size_t)(o0+1)*HW + r    ] = d[nt*4+1];
        op[(size_t)o0*HW     + r + 8] = d[nt*4+2];
        op[(size_t)(o0+1)*HW + r + 8] = d[nt*4+3];
    }

    // fused BN partial stats: reuse A region as reduction pad (8 warps x 64 x 2)
    float* red = (float*)(smraw + 2*BCH2);
#pragma unroll
    for (int nt = 0; nt < 8; nt++) {
#pragma unroll
        for (int e = 0; e < 2; e++) {
            float v0 = d[nt*4 + e], v1 = d[nt*4 + 2 + e];
            float sm = v0 + v1, sq = v0*v0 + v1*v1;
#pragma unroll
            for (int o = 4; o <= 16; o <<= 1) {
                sm += __shfl_xor_sync(0xffffffffu, sm, o);
                sq += __shfl_xor_sync(0xffffffffu, sq, o);
            }
            if (r == 0) {
                int o = nt*8 + 2*t + e;
                red[(w*64 + o)*2]     = sm;
                red[(w*64 + o)*2 + 1] = sq;
            }
        }
    }
    __syncthreads();
    if (tid < 64) {
        float sm = 0.f, sq = 0.f;
#pragma unroll
        for (int wi = 0; wi < 8; wi++) {
            sm += red[(wi*64 + tid)*2];
            sq += red[(wi*64 + tid)*2 + 1];
        }
        g_part[tile*128 + tid*2]     = sm;
        g_part[tile*128 + tid*2 + 1] = sq;
    }
}

// ---------------------------------------------------------------------------
// K4: finalize BN stats — one block per channel
// ---------------------------------------------------------------------------
__global__ void k4_finalize(const float* __restrict__ gamma,
                            const float* __restrict__ beta) {
    __shared__ float ssm[256], ssq[256];
    int c = blockIdx.x;
    int tid = threadIdx.x;
    float sm = 0.f, sq = 0.f;
    for (int tt = tid; tt < NT; tt += 256) {
        sm += g_part[tt*128 + c*2];
        sq += g_part[tt*128 + c*2 + 1];
    }
    ssm[tid] = sm; ssq[tid] = sq;
    __syncthreads();
    for (int st = 128; st > 0; st >>= 1) {
        if (tid < st) { ssm[tid] += ssm[tid+st]; ssq[tid] += ssq[tid+st]; }
        __syncthreads();
    }
    if (tid == 0) {
        const float inv = 1.f / (float)PIX;
        float mu  = ssm[0] * inv;
        float var = ssq[0] * inv - mu*mu;
        float sc  = __ldg(gamma + c) * rsqrtf(var + 1e-5f);
        g_scale[c] = sc;
        g_shift[c] = __ldg(beta + c) - mu * sc;
    }
}

// ---------------------------------------------------------------------------
// K5: BN affine + ReLU + 2x2 maxpool
// ---------------------------------------------------------------------------
__global__ void k5_pool(float* __restrict__ out) {
    int idx = blockIdx.x * 256 + threadIdx.x;
    if (idx >= BATCH*COUT*96*96) return;
    int xo = idx % 96;
    int yo = (idx / 96) % 96;
    int c  = (idx / (96*96)) % COUT;
    int b  = idx / (96*96*COUT);
    float sc = g_scale[c], sh = g_shift[c];
    const float* ip = g_mid + ((size_t)(b*COUT + c))*HW + (2*yo)*WW + 2*xo;
    float v0 = fmaxf(fmaf(ip[0],    sc, sh), 0.f);
    float v1 = fmaxf(fmaf(ip[1],    sc, sh), 0.f);
    float v2 = fmaxf(fmaf(ip[WW],   sc, sh), 0.f);
    float v3 = fmaxf(fmaf(ip[WW+1], sc, sh), 0.f);
    out[idx] = fmaxf(fmaxf(v0, v1), fmaxf(v2, v3));
}

// ---------------------------------------------------------------------------
extern "C" void kernel_launch(void* const* d_in, const int* in_sizes, int n_in,
                              void* d_out, int out_size) {
    const float* x     = (const float*)d_in[0];
    const float* wp    = (const float*)d_in[1];
    const float* bp    = (const float*)d_in[2];
    const float* wm    = (const float*)d_in[3];
    const float* bm    = (const float*)d_in[4];
    const float* wc    = (const float*)d_in[5];
    const float* gamma = (const float*)d_in[6];
    const float* beta  = (const float*)d_in[7];
    float* out = (float*)d_out;

    cudaFuncSetAttribute(k1_mma, cudaFuncAttributeMaxDynamicSharedMemorySize, SMEM_K1);
    cudaFuncSetAttribute(k2_mma, cudaFuncAttributeMaxDynamicSharedMemorySize, SMEM_K2);

    k0_prep<<<(18*2048 + 255)/256, 256>>>(wp, wm, wc);
    k1_mma<<<NT, 256, SMEM_K1>>>(x, bp, bm);
    k_probe<<<1, 32>>>();   // keep k2 at ncu capture slot
    k2_mma<<<NT, 256, SMEM_K2>>>(x);
    k4_finalize<<<64, 256>>>(gamma, beta);
    k5_pool<<<(BATCH*COUT*96*96 + 255)/256, 256>>>(out);
}

// round 16
// speedup vs baseline: 1.3435x; 1.1308x over previous
#include <cuda_runtime.h>
#include <cuda_fp16.h>
#include <math.h>
#include <stdint.h>

#define BATCH 4
#define CIN 64
#define COUT 64
#define HH 192
#define WW 192
#define HW (HH*WW)          // 36864
#define CHW (CIN*HW)
#define PIX (BATCH*HW)      // 147456
#define KROWS 576
#define NT (PIX/128)        // 1152 tiles of 128 pixels
#define TPB 288             // tiles per batch image
#define SMEM_A (128*32*4)   // 16384 per A stage
#define BCH2 (64*36*4)      // 9216  per B chunk (k2), pitch 36 u32
#define BCH1 (32*36*4)      // 4608  per B chunk (k1)
#define SMEM_K2 (2*SMEM_A + 2*BCH2)   // 51200
#define SMEM_K1 (2*SMEM_A + 2*BCH1)   // 41984

__device__ __forceinline__ uint32_t smem_u32(const void* p) {
    uint32_t a;
    asm("{ .reg .u64 t; cvta.to.shared.u64 t, %1; cvt.u32.u64 %0, t; }" : "=r"(a) : "l"(p));
    return a;
}
__device__ __forceinline__ uint32_t tf32cvt(float f) {
    uint32_t u; asm("cvt.rna.tf32.f32 %0, %1;" : "=r"(u) : "f"(f)); return u;
}
__device__ __forceinline__ void mma_tf32(float* d, uint32_t a0, uint32_t a1,
                                         uint32_t a2, uint32_t a3,
                                         uint32_t b0, uint32_t b1) {
    asm volatile(
        "mma.sync.aligned.m16n8k8.row.col.f32.tf32.tf32.f32 "
        "{%0,%1,%2,%3}, {%4,%5,%6,%7}, {%8,%9}, {%0,%1,%2,%3};"
        : "+f"(d[0]), "+f"(d[1]), "+f"(d[2]), "+f"(d[3])
        : "r"(a0), "r"(a1), "r"(a2), "r"(a3), "r"(b0), "r"(b1));
}
__device__ __forceinline__ uint32_t swz(uint32_t byte) {
    return byte ^ ((byte >> 3) & 0x70u);
}

// ---- scratch (device globals) ----
__device__ uint32_t g_wB1c[18*1024];        // k1 B chunks: [s][n(32)][ubl(32)]
__device__ uint32_t g_wB2c[18*2048];        // k2 B chunks: [s][n(64)][ubl(32)]
__device__ __half2  g_xh[BATCH*32*HW];      // channel-paired f16 image [b][c/2][pos]
__device__ float    g_off[BATCH*27*HW];
__device__ float    g_mid[BATCH*COUT*HW];
__device__ float    g_part[NT*128];         // per-tile [64ch][sum,sq]
__device__ float    g_scale[COUT];
__device__ float    g_shift[COUT];

// ---------------------------------------------------------------------------
// K0: pack tf32 weight chunk matrices
// ---------------------------------------------------------------------------
__global__ void k0_prep(const float* __restrict__ wp, const float* __restrict__ wm,
                        const float* __restrict__ wc) {
    int i = blockIdx.x * 256 + threadIdx.x;
    if (i < 18*1024) {
        int s = i >> 10, r = i & 1023;
        int n = r >> 5, ubl = r & 31;
        uint32_t val = 0;
        if (n < 27) {
            int u = s*32 + ubl;
            int tap = u >> 6, c = u & 63;
            float w = (n < 18) ? wp[n*KROWS + c*9 + tap] : wm[(n-18)*KROWS + c*9 + tap];
            val = tf32cvt(w);
        }
        g_wB1c[i] = val;
    }
    if (i < 18*2048) {
        int s = i >> 11, r = i & 2047;
        int n = r >> 5, ubl = r & 31;
        int u = s*32 + ubl;
        int tap = u >> 6, c = u & 63;
        g_wB2c[i] = tf32cvt(wc[n*KROWS + c*9 + tap]);
    }
}

// ---------------------------------------------------------------------------
// K0x: build channel-paired f16 image
// ---------------------------------------------------------------------------
__global__ void k0_xpack(const float* __restrict__ x) {
    int i = blockIdx.x * 256 + threadIdx.x;
    if (i >= BATCH*32*HW) return;
    int pos = i % HW;
    int p   = i / HW;
    int c2  = p & 31;
    int b   = p >> 5;
    const float* src = x + ((size_t)(b*64 + c2*2))*HW + pos;
    g_xh[i] = __floats2half2_rn(src[0], src[HW]);
}

// ---------------------------------------------------------------------------
// K1: offset/mask conv as tf32 HMMA GEMM, M=128 tile, streamed B, f16 loads.
// ---------------------------------------------------------------------------
__global__ void __launch_bounds__(256, 2) k1_mma(const float* __restrict__ bp,
                                                 const float* __restrict__ bm) {
    extern __shared__ __align__(1024) char smraw[];
    uint32_t* Bsm = (uint32_t*)smraw;                  // 2 x BCH1
    const uint32_t AbaseS = smem_u32(smraw) + 2*BCH1;

    int tid = threadIdx.x;
    int tile = blockIdx.x;
    int lp   = tid & 127;
    int uh   = tid >> 7;
    int b    = tile / TPB;
    int rembase = (tile - b*TPB) * 128;
    int rem  = rembase + lp;
    int y    = rem / WW, xx = rem - y*WW;
    const __half2* xh = g_xh + (size_t)b*32*HW;

    int lane = tid & 31, w = tid >> 5;
    int r = lane >> 2, t = lane & 3;

    // preload B chunk 0
    {
        uint4 v0 = ((const uint4*)g_wB1c)[tid];
        int n = tid >> 3, ubl = (tid & 7) * 4;
        uint32_t byte = (uint32_t)(n*36 + ubl)*4u;
        asm volatile("st.shared.v4.b32 [%0], {%1,%2,%3,%4};"
            :: "r"(smem_u32(smraw) + byte), "r"(v0.x), "r"(v0.y), "r"(v0.z), "r"(v0.w)
            : "memory");
    }

    float d[16];
#pragma unroll
    for (int i = 0; i < 16; i++) d[i] = 0.f;

#pragma unroll 1
    for (int s = -1; s < 18; s++) {
        int sp = s + 1;
        uint4 bch; bool doB = (sp < 18 && sp > 0);
        if (doB) bch = ((const uint4*)(g_wB1c + sp*1024))[tid];

        if (s >= 0) {
            uint32_t Abuf = AbaseS + (uint32_t)((s & 1) * SMEM_A);
            const uint32_t* Bs = Bsm + (s & 1) * (BCH1/4);
#pragma unroll
            for (int kc = 0; kc < 4; kc++) {
                uint32_t brow = (uint32_t)(w*16 + r)*128u;
                uint32_t bcol = (uint32_t)(kc*8 + t)*4u;
                uint32_t a0, a1, a2, a3;
                asm volatile("ld.shared.b32 %0, [%1];" : "=r"(a0) : "r"(Abuf + swz(brow + bcol)));
                asm volatile("ld.shared.b32 %0, [%1];" : "=r"(a1) : "r"(Abuf + swz(brow + 1024u + bcol)));
                asm volatile("ld.shared.b32 %0, [%1];" : "=r"(a2) : "r"(Abuf + swz(brow + bcol + 16u)));
                asm volatile("ld.shared.b32 %0, [%1];" : "=r"(a3) : "r"(Abuf + swz(brow + 1024u + bcol + 16u)));
                int ubl = kc*8 + t;
#pragma unroll
                for (int nt = 0; nt < 4; nt++) {
                    int nrow = nt*8 + r;
                    uint32_t b0 = Bs[nrow*36 + ubl];
                    uint32_t b1 = Bs[nrow*36 + ubl + 4];
                    mma_tf32(d + nt*4, a0, a1, a2, a3, b0, b1);
                }
            }
        }
        if (sp < 18) {
            int n  = sp >> 1;
            int ty = n / 3, tx = n - 3*ty;
            int iy = y + ty - 1, ix = xx + tx - 1;
            bool valid = (iy >= 0) && (iy < HH) && (ix >= 0) && (ix < WW);
            int chalf = (sp & 1) * 32;
            uint32_t Abuf = AbaseS + (uint32_t)((sp & 1) * SMEM_A);
            const __half2* xs = xh + (iy*WW + ix);
            __half2 z = __float2half2_rn(0.f);
#pragma unroll
            for (int q = 0; q < 4; q++) {
                int c2 = (chalf + uh*16 + q*4) >> 1;
                __half2 h0 = valid ? __ldg(xs + (size_t)c2*HW)     : z;
                __half2 h1 = valid ? __ldg(xs + (size_t)(c2+1)*HW) : z;
                float2 f0 = __half22float2(h0), f1 = __half22float2(h1);
                uint32_t v[4];
                v[0] = tf32cvt(f0.x); v[1] = tf32cvt(f0.y);
                v[2] = tf32cvt(f1.x); v[3] = tf32cvt(f1.y);
                uint32_t byte = swz((uint32_t)lp*128u + (uint32_t)(uh*16 + q*4)*4u);
                asm volatile("st.shared.v4.b32 [%0], {%1,%2,%3,%4};"
                    :: "r"(Abuf + byte), "r"(v[0]), "r"(v[1]), "r"(v[2]), "r"(v[3])
                    : "memory");
            }
            if (doB) {
                int n2 = tid >> 3, ubl = (tid & 7) * 4;
                uint32_t byte = (uint32_t)((sp & 1) * BCH1) + (uint32_t)(n2*36 + ubl)*4u;
                asm volatile("st.shared.v4.b32 [%0], {%1,%2,%3,%4};"
                    :: "r"(smem_u32(smraw) + byte), "r"(bch.x), "r"(bch.y), "r"(bch.z), "r"(bch.w)
                    : "memory");
            }
        }
        __syncthreads();
    }

    float* op = g_off + (size_t)b*27*HW + (rembase + w*16);
#pragma unroll
    for (int nt = 0; nt < 4; nt++) {
#pragma unroll
        for (int e = 0; e < 2; e++) {
            int o = nt*8 + 2*t + e;
            if (o >= 27) continue;
            float add = (o < 18) ? __ldg(bp + o) : __ldg(bm + o - 18);
            float v0 = d[nt*4 + e]     + add;
            float v1 = d[nt*4 + 2 + e] + add;
            if (o >= 18) {
                v0 = 1.f / (1.f + expf(-v0));
                v1 = 1.f / (1.f + expf(-v1));
            }
            op[(size_t)o*HW + r]     = v0;
            op[(size_t)o*HW + r + 8] = v1;
        }
    }
}

// ---------------------------------------------------------------------------
// K2: deformable sampling + main conv, f16 paired gathers, streamed B,
//     fused BN partials. 2 CTAs/SM.
// ---------------------------------------------------------------------------
__global__ void __launch_bounds__(256, 2) k2_mma() {
    extern __shared__ __align__(1024) char smraw[];
    uint32_t* Bsm = (uint32_t*)smraw;                  // 2 x BCH2
    const uint32_t AbaseS = smem_u32(smraw) + 2*BCH2;

    int tid = threadIdx.x;
    int tile = blockIdx.x;
    int lp   = tid & 127;
    int uh   = tid >> 7;
    int b    = tile / TPB;
    int rembase = (tile - b*TPB) * 128;
    int rem  = rembase + lp;
    int y    = rem / WW, xx = rem - y*WW;
    const __half2* xh   = g_xh + (size_t)b*32*HW;
    const float*   offp = g_off + (size_t)b*27*HW + rem;

    int lane = tid & 31, w = tid >> 5;
    int r = lane >> 2, t = lane & 3;

    // preload B chunk 0: 2048 u32 = 512 uint4
    {
        const uint4* src = (const uint4*)g_wB2c;
#pragma unroll
        for (int jj = 0; jj < 2; jj++) {
            int j = tid*2 + jj;
            uint4 v = src[j];
            int n = j >> 3, ubl = (j & 7) * 4;
            uint32_t byte = (uint32_t)(n*36 + ubl)*4u;
            asm volatile("st.shared.v4.b32 [%0], {%1,%2,%3,%4};"
                :: "r"(smem_u32(smraw) + byte), "r"(v.x), "r"(v.y), "r"(v.z), "r"(v.w)
                : "memory");
        }
    }

    float d[32];
#pragma unroll
    for (int i = 0; i < 32; i++) d[i] = 0.f;

    float cw0=0, cw1=0, cw2=0, cw3=0;
    int   co0=0, co1=0, co2=0, co3=0;

#pragma unroll 1
    for (int s = -1; s < 18; s++) {
        int sp = s + 1;
        uint4 bch0, bch1; bool doB = (sp < 18 && sp > 0);
        if (doB) {
            const uint4* src = (const uint4*)(g_wB2c + sp*2048);
            bch0 = src[tid*2];
            bch1 = src[tid*2 + 1];
        }

        if (s >= 0) {
            uint32_t Abuf = AbaseS + (uint32_t)((s & 1) * SMEM_A);
            const uint32_t* Bs = Bsm + (s & 1) * (BCH2/4);
#pragma unroll
            for (int kc = 0; kc < 4; kc++) {
                uint32_t brow = (uint32_t)(w*16 + r)*128u;
                uint32_t bcol = (uint32_t)(kc*8 + t)*4u;
                uint32_t a0, a1, a2, a3;
                asm volatile("ld.shared.b32 %0, [%1];" : "=r"(a0) : "r"(Abuf + swz(brow + bcol)));
                asm volatile("ld.shared.b32 %0, [%1];" : "=r"(a1) : "r"(Abuf + swz(brow + 1024u + bcol)));
                asm volatile("ld.shared.b32 %0, [%1];" : "=r"(a2) : "r"(Abuf + swz(brow + bcol + 16u)));
                asm volatile("ld.shared.b32 %0, [%1];" : "=r"(a3) : "r"(Abuf + swz(brow + 1024u + bcol + 16u)));
                int ubl = kc*8 + t;
#pragma unroll
                for (int nt = 0; nt < 8; nt++) {
                    int nrow = nt*8 + r;
                    uint32_t b0 = Bs[nrow*36 + ubl];
                    uint32_t b1 = Bs[nrow*36 + ubl + 4];
                    mma_tf32(d + nt*4, a0, a1, a2, a3, b0, b1);
                }
            }
        }
        if (sp < 18) {
            int n = sp >> 1;
            if ((sp & 1) == 0) {   // new tap: recompute bilinear corners
                float offy = __ldg(offp + n*HW);
                float offx = __ldg(offp + (9+n)*HW);
                float mm   = __ldg(offp + (18+n)*HW);
                int ty = n / 3, tx = n - 3*ty;
                float py = (float)(y + ty) + offy;
                float px = (float)(xx + tx) + offx;
                float fy = floorf(py), fx = floorf(px);
                float qy0 = fminf(fmaxf(fy,       0.f), 193.f);
                float qy1 = fminf(fmaxf(fy + 1.f, 0.f), 193.f);
                float qx0 = fminf(fmaxf(fx,       0.f), 193.f);
                float qx1 = fminf(fmaxf(fx + 1.f, 0.f), 193.f);
                float pyc = fminf(fmaxf(py, 0.f), 193.f);
                float pxc = fminf(fmaxf(px, 0.f), 193.f);
                float wy0 = 1.f + (qy0 - pyc), wy1 = 1.f - (qy1 - pyc);
                float wx0 = 1.f + (qx0 - pxc), wx1 = 1.f - (qx1 - pxc);
                int iy0 = (int)qy0, iy1 = (int)qy1, ix0 = (int)qx0, ix1 = (int)qx1;
                bool vy0 = (iy0 >= 1) && (iy0 <= 192);
                bool vy1 = (iy1 >= 1) && (iy1 <= 192);
                bool vx0 = (ix0 >= 1) && (ix0 <= 192);
                bool vx1 = (ix1 >= 1) && (ix1 <= 192);
                cw0 = (vy0 && vx0) ? wy0*wx0*mm : 0.f;
                cw1 = (vy0 && vx1) ? wy0*wx1*mm : 0.f;
                cw2 = (vy1 && vx0) ? wy1*wx0*mm : 0.f;
                cw3 = (vy1 && vx1) ? wy1*wx1*mm : 0.f;
                int jy0 = min(max(iy0, 1), 192) - 1;
                int jy1 = min(max(iy1, 1), 192) - 1;
                int jx0 = min(max(ix0, 1), 192) - 1;
                int jx1 = min(max(ix1, 1), 192) - 1;
                co0 = jy0*WW + jx0; co1 = jy0*WW + jx1;
                co2 = jy1*WW + jx0; co3 = jy1*WW + jx1;
            }
            int chalf = (sp & 1) * 32;
            uint32_t Abuf = AbaseS + (uint32_t)((sp & 1) * SMEM_A);
#pragma unroll
            for (int q = 0; q < 4; q++) {
                int c2 = (chalf + uh*16 + q*4) >> 1;
                const __half2* xp0 = xh + (size_t)c2*HW;
                const __half2* xp1 = xp0 + HW;
                float2 a00 = __half22float2(__ldg(xp0 + co0));
                float2 a01 = __half22float2(__ldg(xp0 + co1));
                float2 a02 = __half22float2(__ldg(xp0 + co2));
                float2 a03 = __half22float2(__ldg(xp0 + co3));
                float2 b00 = __half22float2(__ldg(xp1 + co0));
                float2 b01 = __half22float2(__ldg(xp1 + co1));
                float2 b02 = __half22float2(__ldg(xp1 + co2));
                float2 b03 = __half22float2(__ldg(xp1 + co3));
                uint32_t v[4];
                v[0] = tf32cvt(cw0*a00.x + cw1*a01.x + cw2*a02.x + cw3*a03.x);
                v[1] = tf32cvt(cw0*a00.y + cw1*a01.y + cw2*a02.y + cw3*a03.y);
                v[2] = tf32cvt(cw0*b00.x + cw1*b01.x + cw2*b02.x + cw3*b03.x);
                v[3] = tf32cvt(cw0*b00.y + cw1*b01.y + cw2*b02.y + cw3*b03.y);
                uint32_t byte = swz((uint32_t)lp*128u + (uint32_t)(uh*16 + q*4)*4u);
                asm volatile("st.shared.v4.b32 [%0], {%1,%2,%3,%4};"
                    :: "r"(Abuf + byte), "r"(v[0]), "r"(v[1]), "r"(v[2]), "r"(v[3])
                    : "memory");
            }
            if (doB) {
#pragma unroll
                for (int jj = 0; jj < 2; jj++) {
                    int j = tid*2 + jj;
                    uint4 v = jj ? bch1 : bch0;
                    int n2 = j >> 3, ubl = (j & 7) * 4;
                    uint32_t byte = (uint32_t)((sp & 1) * BCH2) + (uint32_t)(n2*36 + ubl)*4u;
                    asm volatile("st.shared.v4.b32 [%0], {%1,%2,%3,%4};"
                        :: "r"(smem_u32(smraw) + byte), "r"(v.x), "r"(v.y), "r"(v.z), "r"(v.w)
                        : "memory");
                }
            }
        }
        __syncthreads();
    }

    // writeout D: warp w owns pixels rembase + w*16 + {r, r+8}
    float* op = g_mid + (size_t)b*COUT*HW + (rembase + w*16);
#pragma unroll
    for (int nt = 0; nt < 8; nt++) {
        int o0 = nt*8 + 2*t;
        op[(size_t)o0*HW     + r    ] = d[nt*4+0];
        op[(size_t)(o0+1)*HW + r    ] = d[nt*4+1];
        op[(size_t)o0*HW     + r + 8] = d[nt*4+2];
        op[(size_t)(o0+1)*HW + r + 8] = d[nt*4+3];
    }

    // fused BN partial stats: reuse A region as reduction pad (8 warps x 64 x 2)
    float* red = (float*)(smraw + 2*BCH2);
#pragma unroll
    for (int nt = 0; nt < 8; nt++) {
#pragma unroll
        for (int e = 0; e < 2; e++) {
            float v0 = d[nt*4 + e], v1 = d[nt*4 + 2 + e];
            float sm = v0 + v1, sq = v0*v0 + v1*v1;
#pragma unroll
            for (int o = 4; o <= 16; o <<= 1) {
                sm += __shfl_xor_sync(0xffffffffu, sm, o);
                sq += __shfl_xor_sync(0xffffffffu, sq, o);
            }
            if (r == 0) {
                int o = nt*8 + 2*t + e;
                red[(w*64 + o)*2]     = sm;
                red[(w*64 + o)*2 + 1] = sq;
            }
        }
    }
    __syncthreads();
    if (tid < 64) {
        float sm = 0.f, sq = 0.f;
#pragma unroll
        for (int wi = 0; wi < 8; wi++) {
            sm += red[(wi*64 + tid)*2];
            sq += red[(wi*64 + tid)*2 + 1];
        }
        g_part[tile*128 + tid*2]     = sm;
        g_part[tile*128 + tid*2 + 1] = sq;
    }
}

// ---------------------------------------------------------------------------
// K4: finalize BN stats — one block per channel
// ---------------------------------------------------------------------------
__global__ void k4_finalize(const float* __restrict__ gamma,
                            const float* __restrict__ beta) {
    __shared__ float ssm[256], ssq[256];
    int c = blockIdx.x;
    int tid = threadIdx.x;
    float sm = 0.f, sq = 0.f;
    for (int tt = tid; tt < NT; tt += 256) {
        sm += g_part[tt*128 + c*2];
        sq += g_part[tt*128 + c*2 + 1];
    }
    ssm[tid] = sm; ssq[tid] = sq;
    __syncthreads();
    for (int st = 128; st > 0; st >>= 1) {
        if (tid < st) { ssm[tid] += ssm[tid+st]; ssq[tid] += ssq[tid+st]; }
        __syncthreads();
    }
    if (tid == 0) {
        const float inv = 1.f / (float)PIX;
        float mu  = ssm[0] * inv;
        float var = ssq[0] * inv - mu*mu;
        float sc  = __ldg(gamma + c) * rsqrtf(var + 1e-5f);
        g_scale[c] = sc;
        g_shift[c] = __ldg(beta + c) - mu * sc;
    }
}

// ---------------------------------------------------------------------------
// K5: BN affine + ReLU + 2x2 maxpool
// ---------------------------------------------------------------------------
__global__ void k5_pool(float* __restrict__ out) {
    int idx = blockIdx.x * 256 + threadIdx.x;
    if (idx >= BATCH*COUT*96*96) return;
    int xo = idx % 96;
    int yo = (idx / 96) % 96;
    int c  = (idx / (96*96)) % COUT;
    int b  = idx / (96*96*COUT);
    float sc = g_scale[c], sh = g_shift[c];
    const float* ip = g_mid + ((size_t)(b*COUT + c))*HW + (2*yo)*WW + 2*xo;
    float v0 = fmaxf(fmaf(ip[0],    sc, sh), 0.f);
    float v1 = fmaxf(fmaf(ip[1],    sc, sh), 0.f);
    float v2 = fmaxf(fmaf(ip[WW],   sc, sh), 0.f);
    float v3 = fmaxf(fmaf(ip[WW+1], sc, sh), 0.f);
    out[idx] = fmaxf(fmaxf(v0, v1), fmaxf(v2, v3));
}

// ---------------------------------------------------------------------------
extern "C" void kernel_launch(void* const* d_in, const int* in_sizes, int n_in,
                              void* d_out, int out_size) {
    const float* x     = (const float*)d_in[0];
    const float* wp    = (const float*)d_in[1];
    const float* bp    = (const float*)d_in[2];
    const float* wm    = (const float*)d_in[3];
    const float* bm    = (const float*)d_in[4];
    const float* wc    = (const float*)d_in[5];
    const float* gamma = (const float*)d_in[6];
    const float* beta  = (const float*)d_in[7];
    float* out = (float*)d_out;

    cudaFuncSetAttribute(k1_mma, cudaFuncAttributeMaxDynamicSharedMemorySize, SMEM_K1);
    cudaFuncSetAttribute(k2_mma, cudaFuncAttributeMaxDynamicSharedMemorySize, SMEM_K2);

    k0_prep<<<(18*2048 + 255)/256, 256>>>(wp, wm, wc);
    k0_xpack<<<(BATCH*32*HW + 255)/256, 256>>>(x);
    k1_mma<<<NT, 256, SMEM_K1>>>(bp, bm);
    k2_mma<<<NT, 256, SMEM_K2>>>();        // 4th launch -> ncu capture slot
    k4_finalize<<<64, 256>>>(gamma, beta);
    k5_pool<<<(BATCH*COUT*96*96 + 255)/256, 256>>>(out);
}